// round 7
// baseline (speedup 1.0000x reference)
#include <cuda_runtime.h>
#include <cuda_bf16.h>
#include <cstdint>

#define NN 256
#define CH 20

// E/bias matrix, bf16, K-concatenated layout: 144 rows x 80 cols:
//   cols 0..25  = hi(E[k]/bias), 26..51 = hi (same), 52..77 = lo, 78..79 = 0
//   row n = (j*9+k9)*4 + i  where p = i*4+j
__device__ __align__(16) __nv_bfloat16 gEB[144 * 80];

__device__ __forceinline__ uint32_t pkbf(__nv_bfloat16 a, __nv_bfloat16 b) {
    return (uint32_t)__bfloat16_as_ushort(a) | ((uint32_t)__bfloat16_as_ushort(b) << 16);
}

__device__ __forceinline__ void mma16816(float& d0, float& d1, float& d2, float& d3,
                                         uint32_t a0, uint32_t a1, uint32_t a2, uint32_t a3,
                                         uint32_t b0, uint32_t b1) {
    asm volatile(
        "mma.sync.aligned.m16n8k16.row.col.f32.bf16.bf16.f32 "
        "{%0,%1,%2,%3}, {%4,%5,%6,%7}, {%8,%9}, {%0,%1,%2,%3};"
        : "+f"(d0), "+f"(d1), "+f"(d2), "+f"(d3)
        : "r"(a0), "r"(a1), "r"(a2), "r"(a3), "r"(b0), "r"(b1));
}

// ---------------------------------------------------------------------------
// Kernel 1: compose W1/W2 -> 5x5 E + bias, K-concatenated bf16 layout.
// ---------------------------------------------------------------------------
__global__ void k_precompute(const float* __restrict__ W1, const float* __restrict__ b1,
                             const float* __restrict__ W2, const float* __restrict__ b2) {
    int w = blockIdx.x * 4 + (threadIdx.x >> 5);
    int lane = threadIdx.x & 31;
    if (w >= 144) return;
    int p = w / 9, k9 = w % 9;

    float e[25];
#pragma unroll
    for (int i = 0; i < 25; i++) e[i] = 0.f;
    float bacc = 0.f;

    if (lane < CH) {
        int c = lane;
        float w1[9];
        const float* w1p = W1 + (p * CH + c) * 9;
#pragma unroll
        for (int a = 0; a < 9; a++) w1[a] = __ldg(w1p + a);
        const float* w2p = W2 + ((p * 9 + k9) * CH + c) * 9;
        float s2 = 0.f;
#pragma unroll
        for (int bq = 0; bq < 9; bq++) {
            float w2v = __ldg(w2p + bq);
            s2 += w2v;
            int by = bq / 3, bx = bq % 3;
#pragma unroll
            for (int a = 0; a < 9; a++) {
                int ay = a / 3, ax = a % 3;
                e[(ay + by) * 5 + (ax + bx)] += w1[a] * w2v;
            }
        }
        bacc = s2 * __ldg(b1 + p * CH + c);
    }
#pragma unroll
    for (int o = 16; o > 0; o >>= 1) {
#pragma unroll
        for (int i = 0; i < 25; i++) e[i] += __shfl_xor_sync(0xFFFFFFFFu, e[i], o);
        bacc += __shfl_xor_sync(0xFFFFFFFFu, bacc, o);
    }

    if (lane == 0) {
        int i = p >> 2, j = p & 3;
        int n = (j * 9 + k9) * 4 + i;
        __nv_bfloat16* d = gEB + n * 80;
        float B = __ldg(b2 + w) + bacc;
#pragma unroll
        for (int q = 0; q < 80; q++) {
            int k = (q < 26) ? q : (q < 52) ? (q - 26) : (q < 78) ? (q - 52) : 26;
            float v = (k < 25) ? e[k] : (k == 25 ? B : 0.f);
            __nv_bfloat16 h = __float2bfloat16(v);
            if (q < 52)      d[q] = (k <= 25) ? h : __ushort_as_bfloat16(0);
            else if (q < 78) d[q] = __float2bfloat16(v - __bfloat162float(h));
            else             d[q] = __ushort_as_bfloat16(0);
        }
    }
}

__device__ __forceinline__ constexpr int OFFJK(int jk) {
    return (jk / 9) * 180 + ((jk % 9) / 3) * 18 + ((jk % 9) % 3);
}

// ---------------------------------------------------------------------------
// Kernel: zero the 1-pixel output ring.
// ---------------------------------------------------------------------------
__global__ void k_zero_ring(float* __restrict__ y) {
    int idx = blockIdx.x * 256 + threadIdx.x;
    if (idx >= 16 * 1020) return;
    int plane = idx / 1020, r = idx % 1020;
    int n, m;
    if (r < 256)       { n = 0;   m = r; }
    else if (r < 512)  { n = 255; m = r - 256; }
    else { int r2 = r - 512; n = 1 + (r2 >> 1); m = (r2 & 1) ? 255 : 0; }
    y[plane * NN * NN + n * NN + m] = 0.f;
}

// ---------------------------------------------------------------------------
// Kernel 2: HMMA K-GEMM (K'=80), two independent accumulator chains per
// n-step (ks 0-2 / ks 3-4) + register double-buffered B fragments.
// ---------------------------------------------------------------------------
__global__ void __launch_bounds__(256, 2) k_main(const float* __restrict__ img,
                                                 const float* __restrict__ x,
                                                 float* __restrict__ y) {
    __shared__ float sImg[240];                       // 12 x 20
    __shared__ float sX[720];                         // 4 x 10 x 18
    __shared__ __align__(16) uint32_t sB[144 * 44];   // row stride 44 words

    const int t = threadIdx.x;
    const int w = t >> 5, lane = t & 31;
    const int g = lane >> 2, tg = lane & 3;
    const int b = blockIdx.z, TR = blockIdx.y * 8, TC = blockIdx.x * 16;

    const float* imgb = img + b * NN * NN;
    for (int i = t; i < 240; i += 256) {
        int rr = i / 20, cc = i % 20;
        int gn = TR + rr - 2, gm = TC + cc - 2;
        float v = 0.f;
        if ((unsigned)gn < NN && (unsigned)gm < NN) v = __ldg(imgb + gn * NN + gm);
        sImg[i] = v;
    }
#pragma unroll
    for (int j = 0; j < 4; j++) {
        const float* xb = x + (b * 4 + j) * NN * NN;
        for (int i = t; i < 180; i += 256) {
            int rr = i / 18, cc = i % 18;
            int gn = TR + rr - 1, gm = TC + cc - 1;
            float v = 0.f;
            if ((unsigned)gn < NN && (unsigned)gm < NN) v = __ldg(xb + gn * NN + gm);
            sX[j * 180 + i] = v;
        }
    }
    {   // stage B (144 x 80 bf16 = 1440 uint4), row stride 44 words
        const uint4* src = reinterpret_cast<const uint4*>(gEB);
        for (int i = t; i < 1440; i += 256) {
            int n = i / 10, q = i % 10;
            uint4 v = __ldg(src + i);
            *reinterpret_cast<uint4*>(&sB[n * 44 + q * 4]) = v;
        }
    }
    __syncthreads();

    // --- build A fragments: 5 K-steps x 4 regs ---
    const int pc0 = g, pc1 = g + 8;
    uint32_t af[5][4];
    {
        auto colv = [&](int pc, int c) -> __nv_bfloat16 {
            if (c >= 78) return __ushort_as_bfloat16(0);
            int k; bool lopart;
            if (c < 26)      { k = c;      lopart = false; }
            else if (c < 52) { k = c - 26; lopart = true;  }
            else             { k = c - 52; lopart = false; }
            float f = (k == 25) ? 1.f : sImg[(w + k / 5) * 20 + pc + (k % 5)];
            __nv_bfloat16 h = __float2bfloat16(f);
            return lopart ? __float2bfloat16(f - __bfloat162float(h)) : h;
        };
#pragma unroll
        for (int ks = 0; ks < 5; ks++) {
            const int c0 = ks * 16 + 2 * tg;
            af[ks][0] = pkbf(colv(pc0, c0),     colv(pc0, c0 + 1));
            af[ks][1] = pkbf(colv(pc1, c0),     colv(pc1, c0 + 1));
            af[ks][2] = pkbf(colv(pc0, c0 + 8), colv(pc0, c0 + 9));
            af[ks][3] = pkbf(colv(pc1, c0 + 8), colv(pc1, c0 + 9));
        }
    }

    float sa0 = 0.f, sb0 = 0.f, sa1 = 0.f, sb1 = 0.f;
    const int th = tg >> 1;
    const int xbase = w * 18;

    // B fragments for ni=0 (double-buffered in registers)
    uint32_t cb[10];
    {
        const int nb = g * 44 + tg;
#pragma unroll
        for (int ks = 0; ks < 5; ks++) {
            cb[2 * ks]     = sB[nb + 8 * ks];
            cb[2 * ks + 1] = sB[nb + 8 * ks + 4];
        }
    }

#pragma unroll
    for (int ni = 0; ni < 18; ni++) {
        uint32_t nb2[10];
        if (ni < 17) {
            const int nb = ((ni + 1) * 8 + g) * 44 + tg;
#pragma unroll
            for (int ks = 0; ks < 5; ks++) {
                nb2[2 * ks]     = sB[nb + 8 * ks];
                nb2[2 * ks + 1] = sB[nb + 8 * ks + 4];
            }
        }

        float dA0 = 0.f, dA1 = 0.f, dA2 = 0.f, dA3 = 0.f;   // ks 0..2
        float dB0 = 0.f, dB1 = 0.f, dB2 = 0.f, dB3 = 0.f;   // ks 3..4
        mma16816(dA0, dA1, dA2, dA3, af[0][0], af[0][1], af[0][2], af[0][3], cb[0], cb[1]);
        mma16816(dB0, dB1, dB2, dB3, af[3][0], af[3][1], af[3][2], af[3][3], cb[6], cb[7]);
        mma16816(dA0, dA1, dA2, dA3, af[1][0], af[1][1], af[1][2], af[1][3], cb[2], cb[3]);
        mma16816(dB0, dB1, dB2, dB3, af[4][0], af[4][1], af[4][2], af[4][3], cb[8], cb[9]);
        mma16816(dA0, dA1, dA2, dA3, af[2][0], af[2][1], af[2][2], af[2][3], cb[4], cb[5]);

        const float d0 = dA0 + dB0;
        const float d1 = dA1 + dB1;
        const float d2 = dA2 + dB2;
        const float d3 = dA3 + dB3;

        const int offA = OFFJK(2 * ni);
        const int offB = OFFJK(2 * ni + 1);
        const int off = (th ? offB : offA) + xbase;
        float xv0 = sX[off + pc0];
        float xv1 = sX[off + pc1];
        sa0 = fmaf(d0, xv0, sa0);
        sb0 = fmaf(d1, xv0, sb0);
        sa1 = fmaf(d2, xv1, sa1);
        sb1 = fmaf(d3, xv1, sb1);

#pragma unroll
        for (int q = 0; q < 10; q++) cb[q] = nb2[q];
    }

    sa0 += __shfl_xor_sync(0xFFFFFFFFu, sa0, 2);
    sb0 += __shfl_xor_sync(0xFFFFFFFFu, sb0, 2);
    sa1 += __shfl_xor_sync(0xFFFFFFFFu, sa1, 2);
    sb1 += __shfl_xor_sync(0xFFFFFFFFu, sb1, 2);

    if (tg < 2) {
        const int ch0 = tg * 2;
        const int gr = TR + w;
        const int gc0 = TC + pc0, gc1 = TC + pc1;
        const bool rr = (gr == 0) | (gr == NN - 1);
        const bool r0 = rr | (gc0 == 0) | (gc0 == NN - 1);
        const bool r1 = rr | (gc1 == 0) | (gc1 == NN - 1);
        float* y0 = y + ((b * 4 + ch0) * NN + gr) * NN;
        float* y1 = y + ((b * 4 + ch0 + 1) * NN + gr) * NN;
        if (!r0) { y0[gc0] = sa0; y1[gc0] = sb0; }
        if (!r1) { y0[gc1] = sa1; y1[gc1] = sb1; }
    }
}

// ---------------------------------------------------------------------------
// Kernel 3: exact two-conv on the 1-pixel border ring (atomicAdd onto zeroed ring).
// ---------------------------------------------------------------------------
__global__ void __launch_bounds__(256) k_border(const float* __restrict__ img,
                                                const float* __restrict__ x,
                                                const float* __restrict__ W1,
                                                const float* __restrict__ b1,
                                                const float* __restrict__ W2,
                                                const float* __restrict__ b2,
                                                float* __restrict__ y) {
    __shared__ __align__(16) float sW1p[20 * 12];
    __shared__ __align__(16) float sW2p[180 * 12];
    __shared__ float sb1[20];
    __shared__ float sb2[9];

    const int p = blockIdx.x;
    const int t = threadIdx.x;
    for (int i = t; i < 240; i += 256) {
        int row = i / 12, q = i % 12;
        sW1p[i] = (q < 9) ? W1[p * 180 + row * 9 + q] : 0.f;
    }
    for (int i = t; i < 2160; i += 256) {
        int row = i / 12, q = i % 12;
        sW2p[i] = (q < 9) ? W2[p * 1620 + row * 9 + q] : 0.f;
    }
    if (t < 20) sb1[t] = b1[p * 20 + t];
    if (t < 9)  sb2[t] = b2[p * 9 + t];
    __syncthreads();

    int idx = blockIdx.y * 256 + t;
    if (idx >= 4080) return;
    int b = idx / 1020;
    int r = idx % 1020;
    int n, m;
    if (r < 256)       { n = 0;   m = r; }
    else if (r < 512)  { n = 255; m = r - 256; }
    else { int r2 = r - 512; n = 1 + (r2 >> 1); m = (r2 & 1) ? 255 : 0; }

    const float* imgb = img + b * NN * NN;
    float ipat[25];
#pragma unroll
    for (int u = 0; u < 5; u++)
#pragma unroll
        for (int v = 0; v < 5; v++) {
            int gn = n + u - 2, gm = m + v - 2;
            ipat[u * 5 + v] = ((unsigned)gn < NN && (unsigned)gm < NN)
                              ? __ldg(imgb + gn * NN + gm) : 0.f;
        }

    float hmask[9];
#pragma unroll
    for (int q = 0; q < 9; q++) {
        int qy = q / 3, qx = q % 3;
        int hn = n + qy - 1, hm = m + qx - 1;
        hmask[q] = ((unsigned)hn < NN && (unsigned)hm < NN) ? 1.f : 0.f;
    }

    float K[9];
#pragma unroll
    for (int k = 0; k < 9; k++) K[k] = sb2[k];

#pragma unroll 1
    for (int c = 0; c < CH; c++) {
        const float4* w1v = reinterpret_cast<const float4*>(sW1p + c * 12);
        float4 wa = w1v[0], wb = w1v[1], wc = w1v[2];
        const float w1r[9] = {wa.x, wa.y, wa.z, wa.w, wb.x, wb.y, wb.z, wb.w, wc.x};

        float h[9];
#pragma unroll
        for (int q = 0; q < 9; q++) {
            int qy = q / 3, qx = q % 3;
            float s = sb1[c];
#pragma unroll
            for (int a = 0; a < 9; a++) {
                int ay = a / 3, ax = a % 3;
                s += w1r[a] * ipat[(qy + ay) * 5 + (qx + ax)];
            }
            h[q] = s * hmask[q];
        }
#pragma unroll
        for (int k = 0; k < 9; k++) {
            const float4* w2v = reinterpret_cast<const float4*>(sW2p + (k * CH + c) * 12);
            float4 va = w2v[0], vb = w2v[1], vc = w2v[2];
            K[k] += va.x * h[0] + va.y * h[1] + va.z * h[2] + va.w * h[3]
                  + vb.x * h[4] + vb.y * h[5] + vb.z * h[6] + vb.w * h[7]
                  + vc.x * h[8];
        }
    }

    const int i = p >> 2, j = p & 3;
    const float* xb = x + (b * 4 + j) * NN * NN;
    float s = 0.f;
#pragma unroll
    for (int k = 0; k < 9; k++) {
        int di = k / 3, dj = k % 3;
        int gn = n + di - 1, gm = m + dj - 1;
        float xv = ((unsigned)gn < NN && (unsigned)gm < NN)
                   ? __ldg(xb + gn * NN + gm) : 0.f;
        s += K[k] * xv;
    }
    atomicAdd(&y[((b * 4 + i) * NN + n) * NN + m], s);
}

// ---------------------------------------------------------------------------
extern "C" void kernel_launch(void* const* d_in, const int* in_sizes, int n_in,
                              void* d_out, int out_size) {
    const float* image = (const float*)d_in[0];
    const float* x     = (const float*)d_in[1];
    const float* W1    = (const float*)d_in[2];
    const float* b1    = (const float*)d_in[3];
    const float* W2    = (const float*)d_in[4];
    const float* b2    = (const float*)d_in[5];
    float* y = (float*)d_out;

    k_precompute<<<36, 128>>>(W1, b1, W2, b2);           // launch 1
    k_zero_ring<<<64, 256>>>(y);                         // launch 2
    dim3 g3(16, 16);
    k_border<<<g3, 256>>>(image, x, W1, b1, W2, b2, y);  // launch 3
    dim3 g2(16, 32, 4);
    k_main<<<g2, 256>>>(image, x, y);                    // launch 4 (profiled)
}